// round 1
// baseline (speedup 1.0000x reference)
#include <cuda_runtime.h>
#include <cstdint>
#include <cstddef>

// ---------------- problem constants ----------------
#define N_  20000
#define E_  640000
// layer1: H=8, C=16 (ROW=128); layer2: H=8, C=64 (ROW=512)

// ---------------- scratch layout (bytes) ----------------
// all offsets multiples of 256
static const size_t O_SRC  = 0;                    // int[2*E]
static const size_t O_DST  = 5120000;              // int[2*E]
static const size_t O_H1   = 10240000;             // float[2*N*128]
static const size_t O_S1S  = 30720000;             // float[2*N*8]
static const size_t O_S1D  = 32000000;
static const size_t O_H1C  = 33280000;             // float[N*128]
static const size_t O_H2   = 43520000;             // float[2*N*512]
static const size_t O_S2S  = 125440000;
static const size_t O_S2D  = 126720000;
static const size_t O_H2C  = 128000000;            // float[N*64]
// zeroed-every-launch block (contiguous):
static const size_t O_Z1   = 133120000;            // float[2*N*8]
static const size_t O_ACC1 = 134400000;            // float[2*N*128]
static const size_t O_Z2   = 154880000;            // float[2*N*8]
static const size_t O_ACC2 = 156160000;            // float[2*N*64]
static const size_t SCRATCH_BYTES = 166400000;
static const size_t ZERO_FLOATS   = (SCRATCH_BYTES - O_Z1) / 4;  // 8,320,000

__device__ __align__(256) unsigned char g_scratch[SCRATCH_BYTES];
__device__ int g_mode;   // 1 = int64 indices, 0 = int32

// ---------------- small helpers ----------------
__device__ __forceinline__ float eluf(float x) { return x > 0.f ? x : expm1f(x); }
__device__ __forceinline__ float lrelu(float x) { return x > 0.f ? x : 0.2f * x; }

// ---------------- index dtype detection ----------------
__global__ void k_detect(const unsigned int* p) {
    if (threadIdx.x == 0) {
        int is64 = 1;
        for (int i = 1; i < 64; i += 2)
            if (p[i] != 0u) is64 = 0;
        g_mode = is64;
    }
}

__global__ void k_cvt(const void* pa, const void* pb, int* src, int* dst) {
    int t = blockIdx.y;
    const void* p = t ? pb : pa;
    int i = blockIdx.x * blockDim.x + threadIdx.x;
    if (i >= E_) return;
    int s, d;
    if (g_mode) {
        const long long* q = (const long long*)p;
        s = (int)q[i]; d = (int)q[E_ + i];
    } else {
        const int* q = (const int*)p;
        s = q[i]; d = q[E_ + i];
    }
    src[t * E_ + i] = s;
    dst[t * E_ + i] = d;
}

// ---------------- zero accumulators ----------------
__global__ void k_zero(float4* p, int n4) {
    int i = blockIdx.x * blockDim.x + threadIdx.x;
    int stride = gridDim.x * blockDim.x;
    for (; i < n4; i += stride) p[i] = make_float4(0.f, 0.f, 0.f, 0.f);
}

// ---------------- SGEMM: C[b] = A @ B[b], block tile 128x128, thread 8x8 ----------------
template<int K>
__global__ void __launch_bounds__(256) k_sgemm(
    const float* __restrict__ A, const float* __restrict__ B,
    float* __restrict__ C, int n, int M)
{
    __shared__ float As[16][128];
    __shared__ float Bs[16][128];
    const int tid = threadIdx.x;
    const int rquad = (tid >> 4) << 2;   // 0..60 step 4
    const int cquad = (tid & 15) << 2;   // 0..60 step 4
    const int rowBase = blockIdx.x * 128;
    const int colBase = blockIdx.y * 128;
    const int b = blockIdx.z;
    const float* Bb = B + (size_t)b * K * M + colBase;
    float* Cb = C + (size_t)b * (size_t)n * M + colBase;

    float acc[8][8];
#pragma unroll
    for (int i = 0; i < 8; i++)
#pragma unroll
        for (int j = 0; j < 8; j++) acc[i][j] = 0.f;

    for (int k0 = 0; k0 < K; k0 += 16) {
#pragma unroll
        for (int i = 0; i < 2; i++) {
            int idx = tid + (i << 8);          // 0..511
            int r = idx >> 2;                  // 0..127
            int c = (idx & 3) << 2;            // 0,4,8,12
            float4 v = make_float4(0.f, 0.f, 0.f, 0.f);
            int gr = rowBase + r;
            if (gr < n) v = *(const float4*)(A + (size_t)gr * K + k0 + c);
            As[c + 0][r] = v.x; As[c + 1][r] = v.y;
            As[c + 2][r] = v.z; As[c + 3][r] = v.w;
        }
#pragma unroll
        for (int i = 0; i < 2; i++) {
            int idx = tid + (i << 8);
            int r = idx >> 5;                  // 0..15
            int c = (idx & 31) << 2;           // 0..124
            float4 v = *(const float4*)(Bb + (size_t)(k0 + r) * M + c);
            *(float4*)&Bs[r][c] = v;
        }
        __syncthreads();
#pragma unroll
        for (int kk = 0; kk < 16; kk++) {
            float a[8], bb[8];
            *(float4*)&a[0]  = *(const float4*)&As[kk][rquad];
            *(float4*)&a[4]  = *(const float4*)&As[kk][rquad + 64];
            *(float4*)&bb[0] = *(const float4*)&Bs[kk][cquad];
            *(float4*)&bb[4] = *(const float4*)&Bs[kk][cquad + 64];
#pragma unroll
            for (int i = 0; i < 8; i++)
#pragma unroll
                for (int j = 0; j < 8; j++)
                    acc[i][j] = fmaf(a[i], bb[j], acc[i][j]);
        }
        __syncthreads();
    }
#pragma unroll
    for (int i = 0; i < 8; i++) {
        int gr = rowBase + rquad + (i < 4 ? i : 64 + i - 4);
        if (gr < n) {
            *(float4*)(Cb + (size_t)gr * M + cquad) =
                make_float4(acc[i][0], acc[i][1], acc[i][2], acc[i][3]);
            *(float4*)(Cb + (size_t)gr * M + cquad + 64) =
                make_float4(acc[i][4], acc[i][5], acc[i][6], acc[i][7]);
        }
    }
}

// ---------------- attention scores s_src/s_dst: one warp per node ----------------
template<int C>
__global__ void k_scores(const float* __restrict__ h,
                         const float* __restrict__ a_src,
                         const float* __restrict__ a_dst,
                         float* __restrict__ ss, float* __restrict__ sd)
{
    const int ROW = 8 * C;
    int wid = (blockIdx.x * blockDim.x + threadIdx.x) >> 5;
    int lane = threadIdx.x & 31;
    int t = blockIdx.y;
    if (wid >= N_) return;
    const float* hr = h + (size_t)t * N_ * ROW + (size_t)wid * ROW;
    const float* as = a_src + t * ROW;
    const float* ad = a_dst + t * ROW;
    int head = lane >> 2;
    float ps = 0.f, pd = 0.f;
#pragma unroll
    for (int i = 0; i < C / 16; i++) {
        int off = lane * (ROW / 32) + i * 4;   // same as head*C + (lane&3)*(C/4) + i*4
        float4 v = *(const float4*)(hr + off);
        float4 w = *(const float4*)(as + off);
        float4 u = *(const float4*)(ad + off);
        ps += v.x * w.x + v.y * w.y + v.z * w.z + v.w * w.w;
        pd += v.x * u.x + v.y * u.y + v.z * u.z + v.w * u.w;
    }
    ps += __shfl_xor_sync(0xffffffffu, ps, 1);
    ps += __shfl_xor_sync(0xffffffffu, ps, 2);
    pd += __shfl_xor_sync(0xffffffffu, pd, 1);
    pd += __shfl_xor_sync(0xffffffffu, pd, 2);
    if ((lane & 3) == 0) {
        ss[t * N_ * 8 + wid * 8 + head] = ps;
        sd[t * N_ * 8 + wid * 8 + head] = pd;
    }
}

// ---------------- softmax denominator: one thread per (edge, head) ----------------
__global__ void k_edge_z(const int* __restrict__ src, const int* __restrict__ dst,
                         const float* __restrict__ ss, const float* __restrict__ sd,
                         float* z)
{
    int i = blockIdx.x * blockDim.x + threadIdx.x;
    if (i >= E_ * 8) return;
    int t = blockIdx.y;
    int e = i >> 3, h = i & 7;
    int s = __ldg(&src[t * E_ + e]);
    int d = __ldg(&dst[t * E_ + e]);
    float ev = lrelu(ss[t * N_ * 8 + s * 8 + h] + sd[t * N_ * 8 + d * 8 + h]);
    atomicAdd(&z[t * N_ * 8 + d * 8 + h], __expf(ev));
}

// ---------------- layer-1 aggregate: one warp per edge, ROW=128, concat ----------------
__global__ void k_agg1(const int* __restrict__ src, const int* __restrict__ dst,
                       const float* __restrict__ ss, const float* __restrict__ sd,
                       const float* __restrict__ z, const float* __restrict__ h,
                       float* acc)
{
    int wid = (blockIdx.x * blockDim.x + threadIdx.x) >> 5;
    int lane = threadIdx.x & 31;
    int t = blockIdx.y;
    if (wid >= E_) return;
    int s = src[t * E_ + wid], d = dst[t * E_ + wid];
    float alpha = 0.f;
    if (lane < 8) {
        float ev = lrelu(ss[t * N_ * 8 + s * 8 + lane] + sd[t * N_ * 8 + d * 8 + lane]);
        alpha = __expf(ev) / z[t * N_ * 8 + d * 8 + lane];
    }
    alpha = __shfl_sync(0xffffffffu, alpha, lane >> 2);   // head = (lane*4)/16
    const float4 v = *(const float4*)(h + (size_t)t * N_ * 128 + (size_t)s * 128 + lane * 4);
    float* o = acc + (size_t)t * N_ * 128 + (size_t)d * 128 + lane * 4;
    asm volatile("red.global.add.v4.f32 [%0], {%1,%2,%3,%4};"
                 :: "l"(__cvta_generic_to_global(o)),
                    "f"(v.x * alpha), "f"(v.y * alpha), "f"(v.z * alpha), "f"(v.w * alpha)
                 : "memory");
}

// ---------------- layer-2 aggregate: one warp per edge, head-mean folded ----------------
__global__ void k_agg2(const int* __restrict__ src, const int* __restrict__ dst,
                       const float* __restrict__ ss, const float* __restrict__ sd,
                       const float* __restrict__ z, const float* __restrict__ h,
                       float* acc)
{
    int wid = (blockIdx.x * blockDim.x + threadIdx.x) >> 5;
    int lane = threadIdx.x & 31;
    int t = blockIdx.y;
    if (wid >= E_) return;
    int s = src[t * E_ + wid], d = dst[t * E_ + wid];
    float alpha = 0.f;
    if (lane < 8) {
        float ev = lrelu(ss[t * N_ * 8 + s * 8 + lane] + sd[t * N_ * 8 + d * 8 + lane]);
        alpha = 0.125f * __expf(ev) / z[t * N_ * 8 + d * 8 + lane];   // fold mean over 8 heads
    }
    float al[8];
#pragma unroll
    for (int hh = 0; hh < 8; hh++) al[hh] = __shfl_sync(0xffffffffu, alpha, hh);
    const float* hr = h + (size_t)t * N_ * 512 + (size_t)s * 512;
    float ax = 0.f, ay = 0.f;
#pragma unroll
    for (int hh = 0; hh < 8; hh++) {
        float2 v = *(const float2*)(hr + hh * 64 + lane * 2);
        ax = fmaf(al[hh], v.x, ax);
        ay = fmaf(al[hh], v.y, ay);
    }
    float* o = acc + (size_t)t * N_ * 64 + (size_t)d * 64 + lane * 2;
    asm volatile("red.global.add.v2.f32 [%0], {%1,%2};"
                 :: "l"(__cvta_generic_to_global(o)), "f"(ax), "f"(ay)
                 : "memory");
}

// ---------------- hetero-mean + bias + ELU ----------------
__global__ void k_comb1(const float* __restrict__ acc, const float* __restrict__ b,
                        float* __restrict__ out)
{
    int i = blockIdx.x * blockDim.x + threadIdx.x;   // float4 index over N*32
    if (i >= N_ * 32) return;
    int c4 = i & 31;
    float4 a0 = ((const float4*)acc)[i];
    float4 a1 = ((const float4*)acc)[N_ * 32 + i];
    float4 b0 = ((const float4*)b)[c4];
    float4 b1 = ((const float4*)b)[32 + c4];
    float4 r;
    r.x = eluf(0.5f * (a0.x + a1.x + b0.x + b1.x));
    r.y = eluf(0.5f * (a0.y + a1.y + b0.y + b1.y));
    r.z = eluf(0.5f * (a0.z + a1.z + b0.z + b1.z));
    r.w = eluf(0.5f * (a0.w + a1.w + b0.w + b1.w));
    ((float4*)out)[i] = r;
}

__global__ void k_comb2(const float* __restrict__ acc, const float* __restrict__ b,
                        float* __restrict__ out)
{
    int i = blockIdx.x * blockDim.x + threadIdx.x;   // float4 index over N*16
    if (i >= N_ * 16) return;
    int c4 = i & 15;
    float4 a0 = ((const float4*)acc)[i];
    float4 a1 = ((const float4*)acc)[N_ * 16 + i];
    float4 b0 = ((const float4*)b)[c4];
    float4 b1 = ((const float4*)b)[16 + c4];
    float4 r;
    r.x = eluf(0.5f * (a0.x + a1.x + b0.x + b1.x));
    r.y = eluf(0.5f * (a0.y + a1.y + b0.y + b1.y));
    r.z = eluf(0.5f * (a0.z + a1.z + b0.z + b1.z));
    r.w = eluf(0.5f * (a0.w + a1.w + b0.w + b1.w));
    ((float4*)out)[i] = r;
}

// ---------------- classifier: warp per node ----------------
__global__ void k_classifier(const float* __restrict__ h,
                             const float* __restrict__ Wc1, const float* __restrict__ bc1,
                             const float* __restrict__ Wc2, const float* __restrict__ bc2,
                             float* __restrict__ out)
{
    int wid = (blockIdx.x * blockDim.x + threadIdx.x) >> 5;
    int lane = threadIdx.x & 31;
    if (wid >= N_) return;
    const float* hr = h + (size_t)wid * 64;
    float acc = bc1[lane];
#pragma unroll
    for (int c = 0; c < 64; c++)
        acc = fmaf(hr[c], Wc1[c * 32 + lane], acc);
    acc = fmaxf(acc, 0.f);
    float p0 = acc * Wc2[lane * 2];
    float p1 = acc * Wc2[lane * 2 + 1];
#pragma unroll
    for (int o = 16; o >= 1; o >>= 1) {
        p0 += __shfl_xor_sync(0xffffffffu, p0, o);
        p1 += __shfl_xor_sync(0xffffffffu, p1, o);
    }
    if (lane == 0) {
        out[wid * 2 + 0] = p0 + bc2[0];
        out[wid * 2 + 1] = p1 + bc2[1];
    }
}

// ---------------- launch ----------------
extern "C" void kernel_launch(void* const* d_in, const int* in_sizes, int n_in,
                              void* d_out, int out_size)
{
    const float* x    = (const float*)d_in[0];
    const void*  eia  = d_in[1];
    const void*  eib  = d_in[2];
    const float* W1   = (const float*)d_in[3];
    const float* a1s  = (const float*)d_in[4];
    const float* a1d  = (const float*)d_in[5];
    const float* b1   = (const float*)d_in[6];
    const float* W2   = (const float*)d_in[7];
    const float* a2s  = (const float*)d_in[8];
    const float* a2d  = (const float*)d_in[9];
    const float* b2   = (const float*)d_in[10];
    const float* Wc1  = (const float*)d_in[11];
    const float* bc1  = (const float*)d_in[12];
    const float* Wc2  = (const float*)d_in[13];
    const float* bc2  = (const float*)d_in[14];
    float* out = (float*)d_out;

    void* basev = nullptr;
    cudaGetSymbolAddress(&basev, g_scratch);
    unsigned char* base = (unsigned char*)basev;

    int*   p_src  = (int*)(base + O_SRC);
    int*   p_dst  = (int*)(base + O_DST);
    float* p_h1   = (float*)(base + O_H1);
    float* p_s1s  = (float*)(base + O_S1S);
    float* p_s1d  = (float*)(base + O_S1D);
    float* p_h1c  = (float*)(base + O_H1C);
    float* p_h2   = (float*)(base + O_H2);
    float* p_s2s  = (float*)(base + O_S2S);
    float* p_s2d  = (float*)(base + O_S2D);
    float* p_h2c  = (float*)(base + O_H2C);
    float* p_z1   = (float*)(base + O_Z1);
    float* p_acc1 = (float*)(base + O_ACC1);
    float* p_z2   = (float*)(base + O_Z2);
    float* p_acc2 = (float*)(base + O_ACC2);

    // index handling
    k_detect<<<1, 32>>>((const unsigned int*)eia);
    k_cvt<<<dim3((E_ + 255) / 256, 2), 256>>>(eia, eib, p_src, p_dst);

    // zero z1/acc1/z2/acc2 (contiguous block)
    k_zero<<<2048, 256>>>((float4*)p_z1, (int)(ZERO_FLOATS / 4));

    // ---- layer 1 ----
    k_sgemm<256><<<dim3(157, 1, 2), 256>>>(x, W1, p_h1, N_, 128);
    k_scores<16><<<dim3((N_ + 7) / 8, 2), 256>>>(p_h1, a1s, a1d, p_s1s, p_s1d);
    k_edge_z<<<dim3(E_ * 8 / 256, 2), 256>>>(p_src, p_dst, p_s1s, p_s1d, p_z1);
    k_agg1<<<dim3(E_ / 8, 2), 256>>>(p_src, p_dst, p_s1s, p_s1d, p_z1, p_h1, p_acc1);
    k_comb1<<<(N_ * 32 + 255) / 256, 256>>>(p_acc1, b1, p_h1c);

    // ---- layer 2 ----
    k_sgemm<128><<<dim3(157, 4, 2), 256>>>(p_h1c, W2, p_h2, N_, 512);
    k_scores<64><<<dim3((N_ + 7) / 8, 2), 256>>>(p_h2, a2s, a2d, p_s2s, p_s2d);
    k_edge_z<<<dim3(E_ * 8 / 256, 2), 256>>>(p_src, p_dst, p_s2s, p_s2d, p_z2);
    k_agg2<<<dim3(E_ / 8, 2), 256>>>(p_src, p_dst, p_s2s, p_s2d, p_z2, p_h2, p_acc2);
    k_comb2<<<(N_ * 16 + 255) / 256, 256>>>(p_acc2, b2, p_h2c);

    // ---- classifier ----
    k_classifier<<<(N_ * 32 + 255) / 256, 256>>>(p_h2c, Wc1, bc1, Wc2, bc2, out);
}